// round 7
// baseline (speedup 1.0000x reference)
#include <cuda_runtime.h>
#include <cuda_fp16.h>
#include <cuda_fp8.h>
#include <mma.h>

using namespace nvcuda;

#define GN 3
constexpr int NN = 16512;     // K + EXER entities  (= 129 * 128 exactly)
constexpr int KD = 128;       // embedding dim
constexpr int EE = 400000;    // edges per graph (divisible by 8)
constexpr int BB = 4096;      // batch
constexpr int TT = 204800;    // history length
constexpr int H1 = 512;
constexpr int H2 = 216;
constexpr int H2P = 224;      // padded to 14*16

// ---------------- scratch (static device globals; no allocation) ----------------
__device__ int            d_deg_s[GN][NN];
__device__ int            d_deg_d[GN][NN];
__device__ int            d_rowp[GN][NN + 1];
__device__ int            d_cur[GN][NN];
__device__ unsigned       d_csr4[GN][EE + 16]; // src:16 | fp16 rsqrt(deg_s[src]):16
__device__ unsigned char  d_h8a[NN * KD];  // fp8 e4m3 activations (gather source)
__device__ unsigned char  d_h8b[NN * KD];
__device__ __half         d_aggh[GN][NN * KD];   // fp16 aggregation (A for tensor GEMM)
__device__ __half         d_Wh[GN * 4 * KD * KD];// fp16 GCN weights [g][l][k][n]
__device__ float          d_biasC[4][KD];        // per-layer combined bias (sum over g)
__device__ __half         d_W1h[KD * H1];
__device__ __half         d_W2h[H1 * H2P];       // zero-padded cols
__device__ float          d_sumA[NN * KD];  // entity_emb + h1+h2+h3+h4  (full = /5)
__device__ float          d_sumL[NN * KD];  // h3 (partial)
__device__ __half         d_sumLh[NN * KD]; // h3 + h4 fp16 (disc_full*2) for k_stu
__device__ float          d_stu[BB * KD];
__device__ int            d_segs[BB + 1];
__device__ float          d_cvec[2 * KD];
__device__ __half         d_xh[BB * KD];
__device__ __half         d_x1h[BB * H1];
__device__ float          d_x2[BB * H2];

__device__ __forceinline__ float sigm(float x) { return 1.f / (1.f + __expf(-x)); }

// ---------------- CSR build ----------------
__global__ void k_zero_deg() {
    int i = blockIdx.x * blockDim.x + threadIdx.x;
    if (i < GN * NN) { ((int*)d_deg_s)[i] = 0; ((int*)d_deg_d)[i] = 0; }
}

// 8 edges per thread -> MLP=8 on the L2 atomics
__global__ void k_degree(const int* __restrict__ s0, const int* __restrict__ d0,
                         const int* __restrict__ s1, const int* __restrict__ d1,
                         const int* __restrict__ s2, const int* __restrict__ d2) {
    int i = blockIdx.x * blockDim.x + threadIdx.x;
    const int Q = EE / 8;
    if (i >= GN * Q) return;
    int g = i / Q, e8 = (i - g * Q) * 8;
    const int* S = (g == 0) ? s0 : (g == 1) ? s1 : s2;
    const int* D = (g == 0) ? d0 : (g == 1) ? d1 : d2;
    int4 sa = *(const int4*)&S[e8];
    int4 sb = *(const int4*)&S[e8 + 4];
    int4 da = *(const int4*)&D[e8];
    int4 db = *(const int4*)&D[e8 + 4];
    atomicAdd(&d_deg_s[g][sa.x], 1); atomicAdd(&d_deg_s[g][sa.y], 1);
    atomicAdd(&d_deg_s[g][sa.z], 1); atomicAdd(&d_deg_s[g][sa.w], 1);
    atomicAdd(&d_deg_s[g][sb.x], 1); atomicAdd(&d_deg_s[g][sb.y], 1);
    atomicAdd(&d_deg_s[g][sb.z], 1); atomicAdd(&d_deg_s[g][sb.w], 1);
    atomicAdd(&d_deg_d[g][da.x], 1); atomicAdd(&d_deg_d[g][da.y], 1);
    atomicAdd(&d_deg_d[g][da.z], 1); atomicAdd(&d_deg_d[g][da.w], 1);
    atomicAdd(&d_deg_d[g][db.x], 1); atomicAdd(&d_deg_d[g][db.y], 1);
    atomicAdd(&d_deg_d[g][db.z], 1); atomicAdd(&d_deg_d[g][db.w], 1);
}

// exclusive scan of in-degree -> row_ptr (+cursor copy). one block per graph, 1024 thr.
__global__ void k_scan() {
    __shared__ int sA[1024], sB[1024];
    int g = blockIdx.x, t = threadIdx.x;
    const int CH = (NN + 1023) / 1024;   // 17
    int base = t * CH;
    int s = 0;
    for (int i = 0; i < CH; i++) { int idx = base + i; if (idx < NN) s += d_deg_d[g][idx]; }
    sA[t] = s;
    __syncthreads();
    int* a = sA; int* b = sB;
    for (int off = 1; off < 1024; off <<= 1) {
        b[t] = a[t] + ((t >= off) ? a[t - off] : 0);
        __syncthreads();
        int* tmp = a; a = b; b = tmp;
    }
    int incl = a[t];
    int total = a[1023];
    int run = incl - s;
    for (int i = 0; i < CH; i++) {
        int idx = base + i;
        if (idx < NN) { d_rowp[g][idx] = run; d_cur[g][idx] = run; run += d_deg_d[g][idx]; }
    }
    if (t == 0) d_rowp[g][NN] = total;
}

// 8 edges per thread: deg_s gather + atomic cursor + 4-byte scatter
__global__ void k_fill(const int* __restrict__ s0, const int* __restrict__ d0,
                       const int* __restrict__ s1, const int* __restrict__ d1,
                       const int* __restrict__ s2, const int* __restrict__ d2) {
    int i = blockIdx.x * blockDim.x + threadIdx.x;
    const int Q = EE / 8;
    if (i >= GN * Q) return;
    int g = i / Q, e8 = (i - g * Q) * 8;
    const int* S = (g == 0) ? s0 : (g == 1) ? s1 : s2;
    const int* D = (g == 0) ? d0 : (g == 1) ? d1 : d2;
    int sv[8], dv[8];
    *(int4*)&sv[0] = *(const int4*)&S[e8];
    *(int4*)&sv[4] = *(const int4*)&S[e8 + 4];
    *(int4*)&dv[0] = *(const int4*)&D[e8];
    *(int4*)&dv[4] = *(const int4*)&D[e8 + 4];
    int ds[8];
#pragma unroll
    for (int q = 0; q < 8; q++) ds[q] = d_deg_s[g][sv[q]];
    int pos[8];
#pragma unroll
    for (int q = 0; q < 8; q++) pos[q] = atomicAdd(&d_cur[g][dv[q]], 1);
#pragma unroll
    for (int q = 0; q < 8; q++) {
        unsigned hb = (unsigned)__half_as_ushort(
            __float2half_rn(rsqrtf((float)max(ds[q], 1))));
        d_csr4[g][pos[q]] = (unsigned)sv[q] | (hb << 16);
    }
}

// init: sumA=emb, sumL=0, h0 = fp8(emb). 4 elements per thread.
__global__ void k_init(const float* __restrict__ ent) {
    int i = blockIdx.x * blockDim.x + threadIdx.x;
    if (i >= NN * KD / 4) return;
    float4 v = ((const float4*)ent)[i];
    ((float4*)d_sumA)[i] = v;
    ((float4*)d_sumL)[i] = make_float4(0.f, 0.f, 0.f, 0.f);
    __nv_fp8x2_storage_t lo =
        __nv_cvt_float2_to_fp8x2(make_float2(v.x, v.y), __NV_SATFINITE, __NV_E4M3);
    __nv_fp8x2_storage_t hi =
        __nv_cvt_float2_to_fp8x2(make_float2(v.z, v.w), __NV_SATFINITE, __NV_E4M3);
    ((unsigned*)d_h8a)[i] = (unsigned)lo | ((unsigned)hi << 16);
}

// one-shot fp16 weight conversion + bias combine + W2 padding
__global__ void k_wconv(const float* __restrict__ gcnW, const float* __restrict__ gcnB,
                        const float* __restrict__ W1, const float* __restrict__ W2) {
    int i = blockIdx.x * blockDim.x + threadIdx.x;
    const int A = GN * 4 * KD * KD;          // 196608
    const int B = A + KD * H1;               // +65536
    const int C = B + H1 * H2P;              // +114688
    const int D = C + 4 * KD;                // +512
    if (i < A) {
        d_Wh[i] = __float2half_rn(gcnW[i]);
    } else if (i < B) {
        int j = i - A;
        d_W1h[j] = __float2half_rn(W1[j]);
    } else if (i < C) {
        int j = i - B;
        int k = j / H2P, n = j - k * H2P;
        d_W2h[j] = __float2half_rn(n < H2 ? W2[k * H2 + n] : 0.f);
    } else if (i < D) {
        int j = i - C;
        int l = j >> 7, col = j & 127;
        d_biasC[l][col] = gcnB[l * KD + col] + gcnB[4 * KD + l * KD + col]
                        + gcnB[8 * KD + l * KD + col];
    }
}

// decode 16 fp8 (uint4) and HFMA2-accumulate with weight w2 into acc[8]
__device__ __forceinline__ void fma16(__half2 acc[8], uint4 v, __half2 w2) {
    const unsigned* p = &v.x;
#pragma unroll
    for (int q = 0; q < 4; q++) {
        unsigned word = p[q];
        __half2_raw hlo = __nv_cvt_fp8x2_to_halfraw2(
            (__nv_fp8x2_storage_t)(word & 0xFFFFu), __NV_E4M3);
        __half2_raw hhi = __nv_cvt_fp8x2_to_halfraw2(
            (__nv_fp8x2_storage_t)(word >> 16), __NV_E4M3);
        acc[2 * q]     = __hfma2(w2, *(__half2*)&hlo, acc[2 * q]);
        acc[2 * q + 1] = __hfma2(w2, *(__half2*)&hhi, acc[2 * q + 1]);
    }
}

// ---------------- GCN aggregation: warp per (g, dst-row) ----------------
// 16 edges per warp iteration; each 8-lane group owns 4 edges (4 gathers in
// flight per lane; rec load -> h load is a 2-level chain, no rs gather).
__global__ void __launch_bounds__(256) k_agg(int layer) {
    int gt = blockIdx.x * blockDim.x + threadIdx.x;
    int w = gt >> 5, lane = gt & 31;
    if (w >= GN * NN) return;
    int g = w / NN, n = w - g * NN;
    const unsigned char* __restrict__ hin = (layer & 1) ? d_h8b : d_h8a;
    int e0 = d_rowp[g][n], e1 = d_rowp[g][n + 1];
    const unsigned* __restrict__ cs = d_csr4[g];
    int grp = lane >> 3, sub = lane & 7;
    int colb = sub * 16;                    // byte offset within 128B row
    __half2 acc[8];
#pragma unroll
    for (int j = 0; j < 8; j++) acc[j] = __floats2half2_rn(0.f, 0.f);

    for (int base = e0; base < e1; base += 16) {
        int eb = base + 4 * grp;
        unsigned r0 = cs[eb], r1 = cs[eb + 1], r2 = cs[eb + 2], r3 = cs[eb + 3];
        uint4 v0 = *(const uint4*)(hin + (int)(r0 & 0xFFFFu) * KD + colb);
        uint4 v1 = *(const uint4*)(hin + (int)(r1 & 0xFFFFu) * KD + colb);
        uint4 v2 = *(const uint4*)(hin + (int)(r2 & 0xFFFFu) * KD + colb);
        uint4 v3 = *(const uint4*)(hin + (int)(r3 & 0xFFFFu) * KD + colb);
        if (eb < e1)
            fma16(acc, v0, __half2half2(__ushort_as_half((unsigned short)(r0 >> 16))));
        if (eb + 1 < e1)
            fma16(acc, v1, __half2half2(__ushort_as_half((unsigned short)(r1 >> 16))));
        if (eb + 2 < e1)
            fma16(acc, v2, __half2half2(__ushort_as_half((unsigned short)(r2 >> 16))));
        if (eb + 3 < e1)
            fma16(acc, v3, __half2half2(__ushort_as_half((unsigned short)(r3 >> 16))));
    }
    // combine the 4 lane groups (all hold same columns)
#pragma unroll
    for (int j = 0; j < 8; j++) {
        unsigned u = *(unsigned*)&acc[j];
        unsigned v = __shfl_xor_sync(0xffffffffu, u, 8);
        __half2 t = __hadd2(acc[j], *(__half2*)&v);
        unsigned u2 = *(unsigned*)&t;
        unsigned v2 = __shfl_xor_sync(0xffffffffu, u2, 16);
        acc[j] = __hadd2(t, *(__half2*)&v2);
    }
    if (grp == 0) {
        float rsd = rsqrtf((float)max(e1 - e0, 1));   // rsqrt(deg_d) row factor
        uint4 o0, o1;
        unsigned* oo = &o0.x;
#pragma unroll
        for (int j = 0; j < 8; j++) {
            float2 f = __half22float2(acc[j]);
            __half2 h = __floats2half2_rn(f.x * rsd, f.y * rsd);
            if (j == 4) oo = &o1.x;
            oo[j & 3] = *(unsigned*)&h;
        }
        __half* dst = &d_aggh[g][n * KD + colb];   // colb halves == 16*sub
        *(uint4*)dst = o0;
        *(uint4*)(dst + 8) = o1;
    }
}

// ---------------- GCN GEMM (tensor cores): h_new = sum_g aggh_g @ Wh_gl + biasC
__global__ void __launch_bounds__(256) k_gemmT(int layer) {
    extern __shared__ char smem[];
    __half* Wsm = (__half*)smem;                // 3*128*128 half = 98304 B
    float* stage = (float*)smem;                // overlay after mainloop
    int tid = threadIdx.x, w = tid >> 5, lane = tid & 31;

    {
        uint4* dst = (uint4*)Wsm;
        for (int i = tid; i < 6144; i += 256) {
            int g = i >> 11, rem = i & 2047;
            dst[i] = ((const uint4*)(d_Wh + (size_t)(g * 4 + layer) * 16384))[rem];
        }
    }
    __syncthreads();

    wmma::fragment<wmma::accumulator, 16, 16, 16, float> c[8];
#pragma unroll
    for (int n = 0; n < 8; n++) wmma::fill_fragment(c[n], 0.f);

    int row0 = blockIdx.x * 128 + w * 16;
    for (int kt = 0; kt < 24; kt++) {
        int g = kt >> 3, ks = (kt & 7) << 4;
        wmma::fragment<wmma::matrix_a, 16, 16, 16, __half, wmma::row_major> a;
        wmma::load_matrix_sync(a, d_aggh[g] + row0 * KD + ks, KD);
#pragma unroll
        for (int n = 0; n < 8; n++) {
            wmma::fragment<wmma::matrix_b, 16, 16, 16, __half, wmma::row_major> b;
            wmma::load_matrix_sync(b, Wsm + g * 16384 + ks * 128 + n * 16, 128);
            wmma::mma_sync(c[n], a, b, c[n]);
        }
    }
    __syncthreads();   // everyone done reading Wsm; reuse as stage

    float* st = stage + w * 2048;
#pragma unroll
    for (int n = 0; n < 8; n++)
        wmma::store_matrix_sync(st + n * 16, c[n], 128, wmma::mem_row_major);
    __syncwarp();

    int col0 = lane * 4;
    float4 bias = *(const float4*)&d_biasC[layer][col0];
    unsigned char* hout = (layer & 1) ? d_h8a : d_h8b;
#pragma unroll
    for (int r = 0; r < 16; r++) {
        float4 v = *(float4*)&st[r * 128 + col0];
        v.x += bias.x; v.y += bias.y; v.z += bias.z; v.w += bias.w;
        int base = (row0 + r) * KD + col0;
        __nv_fp8x2_storage_t lo =
            __nv_cvt_float2_to_fp8x2(make_float2(v.x, v.y), __NV_SATFINITE, __NV_E4M3);
        __nv_fp8x2_storage_t hi =
            __nv_cvt_float2_to_fp8x2(make_float2(v.z, v.w), __NV_SATFINITE, __NV_E4M3);
        *(unsigned*)&hout[base] = (unsigned)lo | ((unsigned)hi << 16);
        float4 sa = *(float4*)&d_sumA[base];
        sa.x += v.x; sa.y += v.y; sa.z += v.z; sa.w += v.w;
        *(float4*)&d_sumA[base] = sa;
        if (layer == 2) {
            *(float4*)&d_sumL[base] = v;       // h3
        } else if (layer == 3) {
            float4 sl = *(float4*)&d_sumL[base];
            __half2 s01 = __floats2half2_rn(sl.x + v.x, sl.y + v.y);
            __half2 s23 = __floats2half2_rn(sl.z + v.z, sl.w + v.w);
            uint2 sv2;
            sv2.x = *(unsigned*)&s01;
            sv2.y = *(unsigned*)&s23;
            *(uint2*)&d_sumLh[base] = sv2;     // h3+h4 fp16
        }
    }
}

// ---------------- head ----------------
__global__ void k_segstart(const int* __restrict__ seg) {
    int b = blockIdx.x * blockDim.x + threadIdx.x;
    if (b > BB) return;
    int lo = 0, hi = TT;
    while (lo < hi) { int m = (lo + hi) >> 1; if (seg[m] < b) lo = m + 1; else hi = m; }
    d_segs[b] = lo;
}

// stu[b] = mean over history of disc_full[K+hid] ; sumLh fp16 gather (8 B/lane)
__global__ void k_stu(const int* __restrict__ hist) {
    int gt = blockIdx.x * blockDim.x + threadIdx.x;
    int w = gt >> 5, lane = gt & 31;
    if (w >= BB) return;
    int s = d_segs[w], e = d_segs[w + 1];
    const __half* __restrict__ SL = d_sumLh;
    int col = lane * 4;
    float ax = 0.f, ay = 0.f, az = 0.f, aw = 0.f;
    int t = s;
    for (; t + 4 <= e; t += 4) {
        int4 h4 = make_int4(hist[t], hist[t + 1], hist[t + 2], hist[t + 3]);
        uint2 r0 = *(const uint2*)(SL + (KD + h4.x) * KD + col);
        uint2 r1 = *(const uint2*)(SL + (KD + h4.y) * KD + col);
        uint2 r2 = *(const uint2*)(SL + (KD + h4.z) * KD + col);
        uint2 r3 = *(const uint2*)(SL + (KD + h4.w) * KD + col);
        float2 f;
        f = __half22float2(*(__half2*)&r0.x); ax += f.x; ay += f.y;
        f = __half22float2(*(__half2*)&r0.y); az += f.x; aw += f.y;
        f = __half22float2(*(__half2*)&r1.x); ax += f.x; ay += f.y;
        f = __half22float2(*(__half2*)&r1.y); az += f.x; aw += f.y;
        f = __half22float2(*(__half2*)&r2.x); ax += f.x; ay += f.y;
        f = __half22float2(*(__half2*)&r2.y); az += f.x; aw += f.y;
        f = __half22float2(*(__half2*)&r3.x); ax += f.x; ay += f.y;
        f = __half22float2(*(__half2*)&r3.y); az += f.x; aw += f.y;
    }
    for (; t < e; t++) {
        int h = hist[t];
        uint2 r = *(const uint2*)(SL + (KD + h) * KD + col);
        float2 f;
        f = __half22float2(*(__half2*)&r.x); ax += f.x; ay += f.y;
        f = __half22float2(*(__half2*)&r.y); az += f.x; aw += f.y;
    }
    float inv = 0.5f / fmaxf((float)(e - s), 1.f);
    float4 o = make_float4(ax * inv, ay * inv, az * inv, aw * inv);
    *(float4*)&d_stu[w * KD + col] = o;
}

// c_stu[j] = (full row j) . stuW[K:],  c_exer[j] = (full row j) . exeW[K:]   (full = sumA/5)
__global__ void k_cvec(const float* __restrict__ stuW, const float* __restrict__ exeW) {
    int tid = threadIdx.x;                  // 256 threads, 1 block
    int j = tid & 127;
    bool isE = tid >= 128;
    const float* wv = isE ? (exeW + KD) : (stuW + KD);
    float s = 0.f;
    for (int k = 0; k < KD; k++) s += d_sumA[j * KD + k] * wv[k];
    d_cvec[(isE ? KD : 0) + j] = s * 0.2f;
}

__global__ void k_x(const float* __restrict__ fsW, const float* __restrict__ fsB,
                    const float* __restrict__ feW, const float* __restrict__ feB,
                    const float* __restrict__ disc, const int* __restrict__ exid,
                    const float* __restrict__ kn) {
    int gt = blockIdx.x * blockDim.x + threadIdx.x;
    int w = gt >> 5, lane = gt & 31;
    if (w >= BB) return;
    int eid = exid[w];
    float4 sv = ((const float4*)d_stu)[w * 32 + lane];
    float4 ev = ((const float4*)d_sumA)[(KD + eid) * 32 + lane];
    float4 wa = ((const float4*)fsW)[lane];
    float4 wb = ((const float4*)feW)[lane];
    float ps = sv.x * wa.x + sv.y * wa.y + sv.z * wa.z + sv.w * wa.w;
    float pe = (ev.x * wb.x + ev.y * wb.y + ev.z * wb.z + ev.w * wb.w) * 0.2f;
#pragma unroll
    for (int o = 16; o; o >>= 1) {
        ps += __shfl_xor_sync(0xffffffffu, ps, o);
        pe += __shfl_xor_sync(0xffffffffu, pe, o);
    }
    float ed = 10.f * sigm(disc[eid]);
    float4 cs = ((const float4*)d_cvec)[lane];
    float4 ce = ((const float4*)(d_cvec + KD))[lane];
    float4 kv = ((const float4*)kn)[w * 32 + lane];
    float bs = fsB[0], be = feB[0];
    float x0 = ed * (sigm(ps + cs.x + bs) - sigm(pe + ce.x + be)) * kv.x;
    float x1 = ed * (sigm(ps + cs.y + bs) - sigm(pe + ce.y + be)) * kv.y;
    float x2 = ed * (sigm(ps + cs.z + bs) - sigm(pe + ce.z + be)) * kv.z;
    float x3 = ed * (sigm(ps + cs.w + bs) - sigm(pe + ce.w + be)) * kv.w;
    __half2 h01 = __floats2half2_rn(x0, x1);
    __half2 h23 = __floats2half2_rn(x2, x3);
    uint2 hv;
    hv.x = *(unsigned*)&h01;
    hv.y = *(unsigned*)&h23;
    *(uint2*)&d_xh[w * KD + lane * 4] = hv;
}

// MLP layer 1 (tensor): x(4096x128) @ W1(128x512) -> sigmoid -> d_x1h (fp16)
__global__ void __launch_bounds__(256) k_mlp1T(const float* __restrict__ b1) {
    extern __shared__ char smem[];
    __half* Bsm = (__half*)smem;
    float* stage = (float*)smem;
    int tid = threadIdx.x, w = tid >> 5, lane = tid & 31;
    int n0 = blockIdx.y * 128;

    for (int i = tid; i < 2048; i += 256) {
        int k = i >> 4, nq = (i & 15) << 3;
        *(uint4*)&Bsm[k * 128 + nq] = *(const uint4*)&d_W1h[k * H1 + n0 + nq];
    }
    __syncthreads();

    wmma::fragment<wmma::accumulator, 16, 16, 16, float> c[8];
#pragma unroll
    for (int n = 0; n < 8; n++) wmma::fill_fragment(c[n], 0.f);

    int row0 = blockIdx.x * 128 + w * 16;
    for (int kt = 0; kt < 8; kt++) {
        wmma::fragment<wmma::matrix_a, 16, 16, 16, __half, wmma::row_major> a;
        wmma::load_matrix_sync(a, d_xh + row0 * KD + kt * 16, KD);
#pragma unroll
        for (int n = 0; n < 8; n++) {
            wmma::fragment<wmma::matrix_b, 16, 16, 16, __half, wmma::row_major> b;
            wmma::load_matrix_sync(b, Bsm + kt * 16 * 128 + n * 16, 128);
            wmma::mma_sync(c[n], a, b, c[n]);
        }
    }
    __syncthreads();

    float* st = stage + w * 2048;
#pragma unroll
    for (int n = 0; n < 8; n++)
        wmma::store_matrix_sync(st + n * 16, c[n], 128, wmma::mem_row_major);
    __syncwarp();

    int col0 = lane * 4;
    float4 bias = *(const float4*)&b1[n0 + col0];
#pragma unroll
    for (int r = 0; r < 16; r++) {
        float4 v = *(float4*)&st[r * 128 + col0];
        float y0 = sigm(v.x + bias.x);
        float y1 = sigm(v.y + bias.y);
        float y2 = sigm(v.z + bias.z);
        float y3 = sigm(v.w + bias.w);
        __half2 h01 = __floats2half2_rn(y0, y1);
        __half2 h23 = __floats2half2_rn(y2, y3);
        uint2 hv;
        hv.x = *(unsigned*)&h01;
        hv.y = *(unsigned*)&h23;
        *(uint2*)&d_x1h[(row0 + r) * H1 + n0 + col0] = hv;
    }
}

// MLP layer 2 (tensor): x1(4096x512) @ W2pad(512x224) -> sigmoid -> d_x2 (fp32, 216 cols)
__global__ void __launch_bounds__(256) k_mlp2T(const float* __restrict__ b2) {
    extern __shared__ float stage[];    // 8 * 16 * 224 floats = 114688 B
    int tid = threadIdx.x, w = tid >> 5, lane = tid & 31;

    wmma::fragment<wmma::accumulator, 16, 16, 16, float> c[14];
#pragma unroll
    for (int n = 0; n < 14; n++) wmma::fill_fragment(c[n], 0.f);

    int row0 = blockIdx.x * 128 + w * 16;
    for (int kt = 0; kt < 32; kt++) {
        wmma::fragment<wmma::matrix_a, 16, 16, 16, __half, wmma::row_major> a;
        wmma::load_matrix_sync(a, d_x1h + row0 * H1 + kt * 16, H1);
#pragma unroll
        for (int n = 0; n < 14; n++) {
            wmma::fragment<wmma::matrix_b, 16, 16, 16, __half, wmma::row_major> b;
            wmma::load_matrix_sync(b, d_W2h + kt * 16 * H2P + n * 16, H2P);
            wmma::mma_sync(c[n], a, b, c[n]);
        }
    }
    float* st = stage + w * (16 * H2P);
#pragma unroll
    for (int n = 0; n < 14; n++)
        wmma::store_matrix_sync(st + n * 16, c[n], H2P, wmma::mem_row_major);
    __syncwarp();

#pragma unroll
    for (int j = 0; j < 7; j++) {
        int col = lane * 7 + j;
        if (col < H2) {
            float bb = b2[col];
#pragma unroll
            for (int r = 0; r < 16; r++) {
                float v = st[r * H2P + col];
                d_x2[(row0 + r) * H2 + col] = sigm(v + bb);
            }
        }
    }
}

__global__ void k_out(const float* __restrict__ W3, const float* __restrict__ b3,
                      float* __restrict__ out) {
    int gt = blockIdx.x * blockDim.x + threadIdx.x;
    int w = gt >> 5, lane = gt & 31;
    if (w >= BB) return;
    float s = 0.f;
    for (int k = lane; k < H2; k += 32) s += d_x2[w * H2 + k] * W3[k];
#pragma unroll
    for (int o = 16; o; o >>= 1) s += __shfl_xor_sync(0xffffffffu, s, o);
    if (lane == 0) out[w] = sigm(s + b3[0]);
}

// ---------------- launch ----------------
extern "C" void kernel_launch(void* const* d_in, const int* in_sizes, int n_in,
                              void* d_out, int out_size) {
    const float* ent  = (const float*)d_in[0];
    const float* gcnW = (const float*)d_in[1];
    const float* gcnB = (const float*)d_in[2];
    const float* fsW  = (const float*)d_in[3];
    const float* fsB  = (const float*)d_in[4];
    const float* feW  = (const float*)d_in[5];
    const float* feB  = (const float*)d_in[6];
    const float* disc = (const float*)d_in[7];
    const float* W1   = (const float*)d_in[8];
    const float* b1   = (const float*)d_in[9];
    const float* W2   = (const float*)d_in[10];
    const float* b2   = (const float*)d_in[11];
    const float* W3   = (const float*)d_in[12];
    const float* b3   = (const float*)d_in[13];
    const int* ss = (const int*)d_in[14];
    const int* sd = (const int*)d_in[15];
    const int* ps = (const int*)d_in[16];
    const int* pd = (const int*)d_in[17];
    const int* es = (const int*)d_in[18];
    const int* ed = (const int*)d_in[19];
    const int* exid = (const int*)d_in[21];
    const float* kn  = (const float*)d_in[22];
    const int* hid   = (const int*)d_in[23];
    const int* hseg  = (const int*)d_in[24];
    float* out = (float*)d_out;

    cudaFuncSetAttribute(k_gemmT, cudaFuncAttributeMaxDynamicSharedMemorySize, 98304);
    cudaFuncSetAttribute(k_mlp1T, cudaFuncAttributeMaxDynamicSharedMemorySize, 65536);
    cudaFuncSetAttribute(k_mlp2T, cudaFuncAttributeMaxDynamicSharedMemorySize, 114688);

    k_zero_deg<<<(GN * NN + 255) / 256, 256>>>();
    k_degree<<<(GN * (EE / 8) + 255) / 256, 256>>>(ss, sd, ps, pd, es, ed);
    k_scan<<<GN, 1024>>>();
    k_fill<<<(GN * (EE / 8) + 255) / 256, 256>>>(ss, sd, ps, pd, es, ed);
    k_init<<<(NN * KD / 4 + 255) / 256, 256>>>(ent);
    k_wconv<<<(GN * 4 * KD * KD + KD * H1 + H1 * H2P + 4 * KD + 255) / 256, 256>>>(
        gcnW, gcnB, W1, W2);

    for (int l = 0; l < 4; l++) {
        k_agg<<<(GN * NN * 32 + 255) / 256, 256>>>(l);
        k_gemmT<<<NN / 128, 256, 98304>>>(l);
    }

    k_segstart<<<(BB + 1 + 255) / 256, 256>>>(hseg);
    k_stu<<<(BB * 32 + 255) / 256, 256>>>(hid);
    k_cvec<<<1, 256>>>(fsW, feW);
    k_x<<<(BB * 32 + 255) / 256, 256>>>(fsW, fsB, feW, feB, disc, exid, kn);

    dim3 g1(BB / 128, H1 / 128);
    k_mlp1T<<<g1, 256, 65536>>>(b1);
    k_mlp2T<<<BB / 128, 256, 114688>>>(b2);
    k_out<<<(BB * 32 + 255) / 256, 256>>>(W3, b3, out);
}

// round 8
// speedup vs baseline: 1.0164x; 1.0164x over previous
#include <cuda_runtime.h>
#include <cuda_fp16.h>
#include <cuda_fp8.h>
#include <mma.h>

using namespace nvcuda;

#define GN 3
constexpr int NN = 16512;     // K + EXER entities  (= 129 * 128 exactly)
constexpr int KD = 128;       // embedding dim
constexpr int EE = 400000;    // edges per graph (divisible by 8)
constexpr int BB = 4096;      // batch
constexpr int TT = 204800;    // history length
constexpr int H1 = 512;
constexpr int H2 = 216;
constexpr int H2P = 224;      // padded to 14*16

// block partitioning of the fused setup kernel
constexpr int DEG_B  = (GN * (EE / 8) + 255) / 256;            // 586
constexpr int INIT_B = (NN * KD / 4) / 256;                    // 2064
constexpr int WCONV_N = GN * 4 * KD * KD + KD * H1 + H1 * H2P + 4 * KD;
constexpr int WCONV_B = (WCONV_N + 255) / 256;                 // 1474
// k_out fused tail
constexpr int OUT_B  = (BB * 32) / 256;                        // 512
constexpr int ZERO_B = (2 * GN * NN + 255) / 256;              // 388

// ---------------- scratch (static device globals; no allocation) ----------------
// deg arrays: zero at process start (static init) and re-zeroed by the tail of
// every kernel_launch call -> each call starts from zeros deterministically.
__device__ int            d_deg_s[GN][NN];
__device__ int            d_deg_d[GN][NN];
__device__ int            d_rowp[GN][NN + 1];
__device__ int            d_cur[GN][NN];
__device__ unsigned       d_csr4[GN][EE + 16]; // src:16 | fp16 rsqrt(deg_s[src]):16
__device__ unsigned char  d_h8a[NN * KD];  // fp8 e4m3 activations (gather source)
__device__ unsigned char  d_h8b[NN * KD];
__device__ __half         d_aggh[GN][NN * KD];   // fp16 aggregation (A for tensor GEMM)
__device__ __half         d_Wh[GN * 4 * KD * KD];// fp16 GCN weights [g][l][k][n]
__device__ float          d_biasC[4][KD];        // per-layer combined bias (sum over g)
__device__ __half         d_W1h[KD * H1];
__device__ __half         d_W2h[H1 * H2P];       // zero-padded cols
__device__ float          d_sumA[NN * KD];  // entity_emb + h1+h2+h3+h4  (full = /5)
__device__ float          d_sumL[NN * KD];  // h3 (partial)
__device__ __half         d_sumLh[NN * KD]; // h3 + h4 fp16 (disc_full*2) for k_stu
__device__ float          d_stu[BB * KD];
__device__ int            d_segs[BB + 1];
__device__ float          d_cvec[2 * KD];
__device__ __half         d_xh[BB * KD];
__device__ __half         d_x1h[BB * H1];
__device__ float          d_x2[BB * H2];

__device__ __forceinline__ float sigm(float x) { return 1.f / (1.f + __expf(-x)); }

// ---------------- fused setup: degree atomics | h0/sum init | weight conv ------
__global__ void k_setup(const int* __restrict__ s0, const int* __restrict__ d0,
                        const int* __restrict__ s1, const int* __restrict__ d1,
                        const int* __restrict__ s2, const int* __restrict__ d2,
                        const float* __restrict__ ent,
                        const float* __restrict__ gcnW, const float* __restrict__ gcnB,
                        const float* __restrict__ W1, const float* __restrict__ W2) {
    int b = blockIdx.x, tid = threadIdx.x;
    if (b < DEG_B) {
        // degree atomics, 8 edges per thread
        int i = b * 256 + tid;
        const int Q = EE / 8;
        if (i >= GN * Q) return;
        int g = i / Q, e8 = (i - g * Q) * 8;
        const int* S = (g == 0) ? s0 : (g == 1) ? s1 : s2;
        const int* D = (g == 0) ? d0 : (g == 1) ? d1 : d2;
        int4 sa = *(const int4*)&S[e8];
        int4 sb = *(const int4*)&S[e8 + 4];
        int4 da = *(const int4*)&D[e8];
        int4 db = *(const int4*)&D[e8 + 4];
        atomicAdd(&d_deg_s[g][sa.x], 1); atomicAdd(&d_deg_s[g][sa.y], 1);
        atomicAdd(&d_deg_s[g][sa.z], 1); atomicAdd(&d_deg_s[g][sa.w], 1);
        atomicAdd(&d_deg_s[g][sb.x], 1); atomicAdd(&d_deg_s[g][sb.y], 1);
        atomicAdd(&d_deg_s[g][sb.z], 1); atomicAdd(&d_deg_s[g][sb.w], 1);
        atomicAdd(&d_deg_d[g][da.x], 1); atomicAdd(&d_deg_d[g][da.y], 1);
        atomicAdd(&d_deg_d[g][da.z], 1); atomicAdd(&d_deg_d[g][da.w], 1);
        atomicAdd(&d_deg_d[g][db.x], 1); atomicAdd(&d_deg_d[g][db.y], 1);
        atomicAdd(&d_deg_d[g][db.z], 1); atomicAdd(&d_deg_d[g][db.w], 1);
    } else if (b < DEG_B + INIT_B) {
        // init: sumA=emb, sumL=0, h0=fp8(emb); 4 elems/thread
        int i = (b - DEG_B) * 256 + tid;
        float4 v = ((const float4*)ent)[i];
        ((float4*)d_sumA)[i] = v;
        ((float4*)d_sumL)[i] = make_float4(0.f, 0.f, 0.f, 0.f);
        __nv_fp8x2_storage_t lo =
            __nv_cvt_float2_to_fp8x2(make_float2(v.x, v.y), __NV_SATFINITE, __NV_E4M3);
        __nv_fp8x2_storage_t hi =
            __nv_cvt_float2_to_fp8x2(make_float2(v.z, v.w), __NV_SATFINITE, __NV_E4M3);
        ((unsigned*)d_h8a)[i] = (unsigned)lo | ((unsigned)hi << 16);
    } else {
        // weight conversion + bias combine + W2 padding
        int i = (b - DEG_B - INIT_B) * 256 + tid;
        const int A = GN * 4 * KD * KD;
        const int B = A + KD * H1;
        const int C = B + H1 * H2P;
        const int D = C + 4 * KD;
        if (i < A) {
            d_Wh[i] = __float2half_rn(gcnW[i]);
        } else if (i < B) {
            int j = i - A;
            d_W1h[j] = __float2half_rn(W1[j]);
        } else if (i < C) {
            int j = i - B;
            int k = j / H2P, n = j - k * H2P;
            d_W2h[j] = __float2half_rn(n < H2 ? W2[k * H2 + n] : 0.f);
        } else if (i < D) {
            int j = i - C;
            int l = j >> 7, col = j & 127;
            d_biasC[l][col] = gcnB[l * KD + col] + gcnB[4 * KD + l * KD + col]
                            + gcnB[8 * KD + l * KD + col];
        }
    }
}

// exclusive scan of in-degree -> row_ptr (+cursor copy). one block per graph, 1024 thr.
__global__ void k_scan() {
    __shared__ int sA[1024], sB[1024];
    int g = blockIdx.x, t = threadIdx.x;
    const int CH = (NN + 1023) / 1024;   // 17
    int base = t * CH;
    int s = 0;
    for (int i = 0; i < CH; i++) { int idx = base + i; if (idx < NN) s += d_deg_d[g][idx]; }
    sA[t] = s;
    __syncthreads();
    int* a = sA; int* b = sB;
    for (int off = 1; off < 1024; off <<= 1) {
        b[t] = a[t] + ((t >= off) ? a[t - off] : 0);
        __syncthreads();
        int* tmp = a; a = b; b = tmp;
    }
    int incl = a[t];
    int total = a[1023];
    int run = incl - s;
    for (int i = 0; i < CH; i++) {
        int idx = base + i;
        if (idx < NN) { d_rowp[g][idx] = run; d_cur[g][idx] = run; run += d_deg_d[g][idx]; }
    }
    if (t == 0) d_rowp[g][NN] = total;
}

// 8 edges per thread: deg_s gather + atomic cursor + 4-byte scatter
__global__ void k_fill(const int* __restrict__ s0, const int* __restrict__ d0,
                       const int* __restrict__ s1, const int* __restrict__ d1,
                       const int* __restrict__ s2, const int* __restrict__ d2) {
    int i = blockIdx.x * blockDim.x + threadIdx.x;
    const int Q = EE / 8;
    if (i >= GN * Q) return;
    int g = i / Q, e8 = (i - g * Q) * 8;
    const int* S = (g == 0) ? s0 : (g == 1) ? s1 : s2;
    const int* D = (g == 0) ? d0 : (g == 1) ? d1 : d2;
    int sv[8], dv[8];
    *(int4*)&sv[0] = *(const int4*)&S[e8];
    *(int4*)&sv[4] = *(const int4*)&S[e8 + 4];
    *(int4*)&dv[0] = *(const int4*)&D[e8];
    *(int4*)&dv[4] = *(const int4*)&D[e8 + 4];
    int ds[8];
#pragma unroll
    for (int q = 0; q < 8; q++) ds[q] = d_deg_s[g][sv[q]];
    int pos[8];
#pragma unroll
    for (int q = 0; q < 8; q++) pos[q] = atomicAdd(&d_cur[g][dv[q]], 1);
#pragma unroll
    for (int q = 0; q < 8; q++) {
        unsigned hb = (unsigned)__half_as_ushort(
            __float2half_rn(rsqrtf((float)max(ds[q], 1))));
        d_csr4[g][pos[q]] = (unsigned)sv[q] | (hb << 16);
    }
}

// decode 16 fp8 (uint4) and HFMA2-accumulate with weight w2 into acc[8]
__device__ __forceinline__ void fma16(__half2 acc[8], uint4 v, __half2 w2) {
    const unsigned* p = &v.x;
#pragma unroll
    for (int q = 0; q < 4; q++) {
        unsigned word = p[q];
        __half2_raw hlo = __nv_cvt_fp8x2_to_halfraw2(
            (__nv_fp8x2_storage_t)(word & 0xFFFFu), __NV_E4M3);
        __half2_raw hhi = __nv_cvt_fp8x2_to_halfraw2(
            (__nv_fp8x2_storage_t)(word >> 16), __NV_E4M3);
        acc[2 * q]     = __hfma2(w2, *(__half2*)&hlo, acc[2 * q]);
        acc[2 * q + 1] = __hfma2(w2, *(__half2*)&hhi, acc[2 * q + 1]);
    }
}

// ---------------- GCN aggregation: warp per (g, dst-row) ----------------
// 16 edges per warp iteration; each 8-lane group owns 4 edges with OOB indices
// clamped to the last valid edge (same cache line, weight zeroed) -> MLP=4
// with edge-exact bandwidth.
__global__ void __launch_bounds__(256) k_agg(int layer) {
    int gt = blockIdx.x * blockDim.x + threadIdx.x;
    int w = gt >> 5, lane = gt & 31;
    if (w >= GN * NN) return;
    int g = w / NN, n = w - g * NN;
    const unsigned char* __restrict__ hin = (layer & 1) ? d_h8b : d_h8a;
    int e0 = d_rowp[g][n], e1 = d_rowp[g][n + 1];
    const unsigned* __restrict__ cs = d_csr4[g];
    int grp = lane >> 3, sub = lane & 7;
    int colb = sub * 16;                    // byte offset within 128B row
    __half2 acc[8];
#pragma unroll
    for (int j = 0; j < 8; j++) acc[j] = __floats2half2_rn(0.f, 0.f);

    for (int base = e0; base < e1; base += 16) {
        int eb = base + 4 * grp;
        int m = e1 - 1;                     // e1 >= 1 inside this loop
        int i0 = min(eb, m), i1 = min(eb + 1, m);
        int i2 = min(eb + 2, m), i3 = min(eb + 3, m);
        unsigned r0 = cs[i0], r1 = cs[i1], r2 = cs[i2], r3 = cs[i3];
        uint4 v0 = *(const uint4*)(hin + (int)(r0 & 0xFFFFu) * KD + colb);
        uint4 v1 = *(const uint4*)(hin + (int)(r1 & 0xFFFFu) * KD + colb);
        uint4 v2 = *(const uint4*)(hin + (int)(r2 & 0xFFFFu) * KD + colb);
        uint4 v3 = *(const uint4*)(hin + (int)(r3 & 0xFFFFu) * KD + colb);
        unsigned short w0 = (eb     < e1) ? (unsigned short)(r0 >> 16) : (unsigned short)0;
        unsigned short w1 = (eb + 1 < e1) ? (unsigned short)(r1 >> 16) : (unsigned short)0;
        unsigned short w2 = (eb + 2 < e1) ? (unsigned short)(r2 >> 16) : (unsigned short)0;
        unsigned short w3 = (eb + 3 < e1) ? (unsigned short)(r3 >> 16) : (unsigned short)0;
        fma16(acc, v0, __half2half2(__ushort_as_half(w0)));
        fma16(acc, v1, __half2half2(__ushort_as_half(w1)));
        fma16(acc, v2, __half2half2(__ushort_as_half(w2)));
        fma16(acc, v3, __half2half2(__ushort_as_half(w3)));
    }
    // combine the 4 lane groups (all hold same columns)
#pragma unroll
    for (int j = 0; j < 8; j++) {
        unsigned u = *(unsigned*)&acc[j];
        unsigned v = __shfl_xor_sync(0xffffffffu, u, 8);
        __half2 t = __hadd2(acc[j], *(__half2*)&v);
        unsigned u2 = *(unsigned*)&t;
        unsigned v2 = __shfl_xor_sync(0xffffffffu, u2, 16);
        acc[j] = __hadd2(t, *(__half2*)&v2);
    }
    if (grp == 0) {
        float rsd = rsqrtf((float)max(e1 - e0, 1));   // rsqrt(deg_d) row factor
        uint4 o0, o1;
        unsigned* oo = &o0.x;
#pragma unroll
        for (int j = 0; j < 8; j++) {
            float2 f = __half22float2(acc[j]);
            __half2 h = __floats2half2_rn(f.x * rsd, f.y * rsd);
            if (j == 4) oo = &o1.x;
            oo[j & 3] = *(unsigned*)&h;
        }
        __half* dst = &d_aggh[g][n * KD + colb];   // colb halves == 16*sub
        *(uint4*)dst = o0;
        *(uint4*)(dst + 8) = o1;
    }
}

// ---------------- GCN GEMM (tensor cores): h_new = sum_g aggh_g @ Wh_gl + biasC
__global__ void __launch_bounds__(256) k_gemmT(int layer) {
    extern __shared__ char smem[];
    __half* Wsm = (__half*)smem;                // 3*128*128 half = 98304 B
    float* stage = (float*)smem;                // overlay after mainloop
    int tid = threadIdx.x, w = tid >> 5, lane = tid & 31;

    {
        uint4* dst = (uint4*)Wsm;
        for (int i = tid; i < 6144; i += 256) {
            int g = i >> 11, rem = i & 2047;
            dst[i] = ((const uint4*)(d_Wh + (size_t)(g * 4 + layer) * 16384))[rem];
        }
    }
    __syncthreads();

    wmma::fragment<wmma::accumulator, 16, 16, 16, float> c[8];
#pragma unroll
    for (int n = 0; n < 8; n++) wmma::fill_fragment(c[n], 0.f);

    int row0 = blockIdx.x * 128 + w * 16;
    for (int kt = 0; kt < 24; kt++) {
        int g = kt >> 3, ks = (kt & 7) << 4;
        wmma::fragment<wmma::matrix_a, 16, 16, 16, __half, wmma::row_major> a;
        wmma::load_matrix_sync(a, d_aggh[g] + row0 * KD + ks, KD);
#pragma unroll
        for (int n = 0; n < 8; n++) {
            wmma::fragment<wmma::matrix_b, 16, 16, 16, __half, wmma::row_major> b;
            wmma::load_matrix_sync(b, Wsm + g * 16384 + ks * 128 + n * 16, 128);
            wmma::mma_sync(c[n], a, b, c[n]);
        }
    }
    __syncthreads();   // everyone done reading Wsm; reuse as stage

    float* st = stage + w * 2048;
#pragma unroll
    for (int n = 0; n < 8; n++)
        wmma::store_matrix_sync(st + n * 16, c[n], 128, wmma::mem_row_major);
    __syncwarp();

    int col0 = lane * 4;
    float4 bias = *(const float4*)&d_biasC[layer][col0];
    unsigned char* hout = (layer & 1) ? d_h8a : d_h8b;
#pragma unroll
    for (int r = 0; r < 16; r++) {
        float4 v = *(float4*)&st[r * 128 + col0];
        v.x += bias.x; v.y += bias.y; v.z += bias.z; v.w += bias.w;
        int base = (row0 + r) * KD + col0;
        __nv_fp8x2_storage_t lo =
            __nv_cvt_float2_to_fp8x2(make_float2(v.x, v.y), __NV_SATFINITE, __NV_E4M3);
        __nv_fp8x2_storage_t hi =
            __nv_cvt_float2_to_fp8x2(make_float2(v.z, v.w), __NV_SATFINITE, __NV_E4M3);
        *(unsigned*)&hout[base] = (unsigned)lo | ((unsigned)hi << 16);
        float4 sa = *(float4*)&d_sumA[base];
        sa.x += v.x; sa.y += v.y; sa.z += v.z; sa.w += v.w;
        *(float4*)&d_sumA[base] = sa;
        if (layer == 2) {
            *(float4*)&d_sumL[base] = v;       // h3
        } else if (layer == 3) {
            float4 sl = *(float4*)&d_sumL[base];
            __half2 s01 = __floats2half2_rn(sl.x + v.x, sl.y + v.y);
            __half2 s23 = __floats2half2_rn(sl.z + v.z, sl.w + v.w);
            uint2 sv2;
            sv2.x = *(unsigned*)&s01;
            sv2.y = *(unsigned*)&s23;
            *(uint2*)&d_sumLh[base] = sv2;     // h3+h4 fp16
        }
    }
}

// ---------------- head ----------------
__global__ void k_segstart(const int* __restrict__ seg) {
    int b = blockIdx.x * blockDim.x + threadIdx.x;
    if (b > BB) return;
    int lo = 0, hi = TT;
    while (lo < hi) { int m = (lo + hi) >> 1; if (seg[m] < b) lo = m + 1; else hi = m; }
    d_segs[b] = lo;
}

// stu[b] = mean over history of disc_full[K+hid] ; sumLh fp16 gather (8 B/lane)
__global__ void k_stu(const int* __restrict__ hist) {
    int gt = blockIdx.x * blockDim.x + threadIdx.x;
    int w = gt >> 5, lane = gt & 31;
    if (w >= BB) return;
    int s = d_segs[w], e = d_segs[w + 1];
    const __half* __restrict__ SL = d_sumLh;
    int col = lane * 4;
    float ax = 0.f, ay = 0.f, az = 0.f, aw = 0.f;
    int t = s;
    for (; t + 4 <= e; t += 4) {
        int4 h4 = make_int4(hist[t], hist[t + 1], hist[t + 2], hist[t + 3]);
        uint2 r0 = *(const uint2*)(SL + (KD + h4.x) * KD + col);
        uint2 r1 = *(const uint2*)(SL + (KD + h4.y) * KD + col);
        uint2 r2 = *(const uint2*)(SL + (KD + h4.z) * KD + col);
        uint2 r3 = *(const uint2*)(SL + (KD + h4.w) * KD + col);
        float2 f;
        f = __half22float2(*(__half2*)&r0.x); ax += f.x; ay += f.y;
        f = __half22float2(*(__half2*)&r0.y); az += f.x; aw += f.y;
        f = __half22float2(*(__half2*)&r1.x); ax += f.x; ay += f.y;
        f = __half22float2(*(__half2*)&r1.y); az += f.x; aw += f.y;
        f = __half22float2(*(__half2*)&r2.x); ax += f.x; ay += f.y;
        f = __half22float2(*(__half2*)&r2.y); az += f.x; aw += f.y;
        f = __half22float2(*(__half2*)&r3.x); ax += f.x; ay += f.y;
        f = __half22float2(*(__half2*)&r3.y); az += f.x; aw += f.y;
    }
    for (; t < e; t++) {
        int h = hist[t];
        uint2 r = *(const uint2*)(SL + (KD + h) * KD + col);
        float2 f;
        f = __half22float2(*(__half2*)&r.x); ax += f.x; ay += f.y;
        f = __half22float2(*(__half2*)&r.y); az += f.x; aw += f.y;
    }
    float inv = 0.5f / fmaxf((float)(e - s), 1.f);
    float4 o = make_float4(ax * inv, ay * inv, az * inv, aw * inv);
    *(float4*)&d_stu[w * KD + col] = o;
}

// c_stu[j] = (full row j) . stuW[K:],  c_exer[j] = (full row j) . exeW[K:]   (full = sumA/5)
__global__ void k_cvec(const float* __restrict__ stuW, const float* __restrict__ exeW) {
    int tid = threadIdx.x;                  // 256 threads, 1 block
    int j = tid & 127;
    bool isE = tid >= 128;
    const float* wv = isE ? (exeW + KD) : (stuW + KD);
    float s = 0.f;
    for (int k = 0; k < KD; k++) s += d_sumA[j * KD + k] * wv[k];
    d_cvec[(isE ? KD : 0) + j] = s * 0.2f;
}

__global__ void k_x(const float* __restrict__ fsW, const float* __restrict__ fsB,
                    const float* __restrict__ feW, const float* __restrict__ feB,
                    const float* __restrict__ disc, const int* __restrict__ exid,
                    const float* __restrict__ kn) {
    int gt = blockIdx.x * blockDim.x + threadIdx.x;
    int w = gt >> 5, lane = gt & 31;
    if (w >= BB) return;
    int eid = exid[w];
    float4 sv = ((const float4*)d_stu)[w * 32 + lane];
    float4 ev = ((const float4*)d_sumA)[(KD + eid) * 32 + lane];
    float4 wa = ((const float4*)fsW)[lane];
    float4 wb = ((const float4*)feW)[lane];
    float ps = sv.x * wa.x + sv.y * wa.y + sv.z * wa.z + sv.w * wa.w;
    float pe = (ev.x * wb.x + ev.y * wb.y + ev.z * wb.z + ev.w * wb.w) * 0.2f;
#pragma unroll
    for (int o = 16; o; o >>= 1) {
        ps += __shfl_xor_sync(0xffffffffu, ps, o);
        pe += __shfl_xor_sync(0xffffffffu, pe, o);
    }
    float ed = 10.f * sigm(disc[eid]);
    float4 cs = ((const float4*)d_cvec)[lane];
    float4 ce = ((const float4*)(d_cvec + KD))[lane];
    float4 kv = ((const float4*)kn)[w * 32 + lane];
    float bs = fsB[0], be = feB[0];
    float x0 = ed * (sigm(ps + cs.x + bs) - sigm(pe + ce.x + be)) * kv.x;
    float x1 = ed * (sigm(ps + cs.y + bs) - sigm(pe + ce.y + be)) * kv.y;
    float x2 = ed * (sigm(ps + cs.z + bs) - sigm(pe + ce.z + be)) * kv.z;
    float x3 = ed * (sigm(ps + cs.w + bs) - sigm(pe + ce.w + be)) * kv.w;
    __half2 h01 = __floats2half2_rn(x0, x1);
    __half2 h23 = __floats2half2_rn(x2, x3);
    uint2 hv;
    hv.x = *(unsigned*)&h01;
    hv.y = *(unsigned*)&h23;
    *(uint2*)&d_xh[w * KD + lane * 4] = hv;
}

// MLP layer 1 (tensor): x(4096x128) @ W1(128x512) -> sigmoid -> d_x1h (fp16)
__global__ void __launch_bounds__(256) k_mlp1T(const float* __restrict__ b1) {
    extern __shared__ char smem[];
    __half* Bsm = (__half*)smem;
    float* stage = (float*)smem;
    int tid = threadIdx.x, w = tid >> 5, lane = tid & 31;
    int n0 = blockIdx.y * 128;

    for (int i = tid; i < 2048; i += 256) {
        int k = i >> 4, nq = (i & 15) << 3;
        *(uint4*)&Bsm[k * 128 + nq] = *(const uint4*)&d_W1h[k * H1 + n0 + nq];
    }
    __syncthreads();

    wmma::fragment<wmma::accumulator, 16, 16, 16, float> c[8];
#pragma unroll
    for (int n = 0; n < 8; n++) wmma::fill_fragment(c[n], 0.f);

    int row0 = blockIdx.x * 128 + w * 16;
    for (int kt = 0; kt < 8; kt++) {
        wmma::fragment<wmma::matrix_a, 16, 16, 16, __half, wmma::row_major> a;
        wmma::load_matrix_sync(a, d_xh + row0 * KD + kt * 16, KD);
#pragma unroll
        for (int n = 0; n < 8; n++) {
            wmma::fragment<wmma::matrix_b, 16, 16, 16, __half, wmma::row_major> b;
            wmma::load_matrix_sync(b, Bsm + kt * 16 * 128 + n * 16, 128);
            wmma::mma_sync(c[n], a, b, c[n]);
        }
    }
    __syncthreads();

    float* st = stage + w * 2048;
#pragma unroll
    for (int n = 0; n < 8; n++)
        wmma::store_matrix_sync(st + n * 16, c[n], 128, wmma::mem_row_major);
    __syncwarp();

    int col0 = lane * 4;
    float4 bias = *(const float4*)&b1[n0 + col0];
#pragma unroll
    for (int r = 0; r < 16; r++) {
        float4 v = *(float4*)&st[r * 128 + col0];
        float y0 = sigm(v.x + bias.x);
        float y1 = sigm(v.y + bias.y);
        float y2 = sigm(v.z + bias.z);
        float y3 = sigm(v.w + bias.w);
        __half2 h01 = __floats2half2_rn(y0, y1);
        __half2 h23 = __floats2half2_rn(y2, y3);
        uint2 hv;
        hv.x = *(unsigned*)&h01;
        hv.y = *(unsigned*)&h23;
        *(uint2*)&d_x1h[(row0 + r) * H1 + n0 + col0] = hv;
    }
}

// MLP layer 2 (tensor): x1(4096x512) @ W2pad(512x224) -> sigmoid -> d_x2 (fp32, 216 cols)
__global__ void __launch_bounds__(256) k_mlp2T(const float* __restrict__ b2) {
    extern __shared__ float stage[];    // 8 * 16 * 224 floats = 114688 B
    int tid = threadIdx.x, w = tid >> 5, lane = tid & 31;

    wmma::fragment<wmma::accumulator, 16, 16, 16, float> c[14];
#pragma unroll
    for (int n = 0; n < 14; n++) wmma::fill_fragment(c[n], 0.f);

    int row0 = blockIdx.x * 128 + w * 16;
    for (int kt = 0; kt < 32; kt++) {
        wmma::fragment<wmma::matrix_a, 16, 16, 16, __half, wmma::row_major> a;
        wmma::load_matrix_sync(a, d_x1h + row0 * H1 + kt * 16, H1);
#pragma unroll
        for (int n = 0; n < 14; n++) {
            wmma::fragment<wmma::matrix_b, 16, 16, 16, __half, wmma::row_major> b;
            wmma::load_matrix_sync(b, d_W2h + kt * 16 * H2P + n * 16, H2P);
            wmma::mma_sync(c[n], a, b, c[n]);
        }
    }
    float* st = stage + w * (16 * H2P);
#pragma unroll
    for (int n = 0; n < 14; n++)
        wmma::store_matrix_sync(st + n * 16, c[n], H2P, wmma::mem_row_major);
    __syncwarp();

#pragma unroll
    for (int j = 0; j < 7; j++) {
        int col = lane * 7 + j;
        if (col < H2) {
            float bb = b2[col];
#pragma unroll
            for (int r = 0; r < 16; r++) {
                float v = st[r * H2P + col];
                d_x2[(row0 + r) * H2 + col] = sigm(v + bb);
            }
        }
    }
}

// output + deg-array re-zero for the next call (fused tail)
__global__ void k_outz(const float* __restrict__ W3, const float* __restrict__ b3,
                       float* __restrict__ out) {
    int b = blockIdx.x, tid = threadIdx.x;
    if (b < OUT_B) {
        int gt = b * 256 + tid;
        int w = gt >> 5, lane = gt & 31;
        if (w >= BB) return;
        float s = 0.f;
        for (int k = lane; k < H2; k += 32) s += d_x2[w * H2 + k] * W3[k];
#pragma unroll
        for (int o = 16; o; o >>= 1) s += __shfl_xor_sync(0xffffffffu, s, o);
        if (lane == 0) out[w] = sigm(s + b3[0]);
    } else {
        int i = (b - OUT_B) * 256 + tid;
        if (i < GN * NN) ((int*)d_deg_s)[i] = 0;
        else if (i < 2 * GN * NN) ((int*)d_deg_d)[i - GN * NN] = 0;
    }
}

// ---------------- launch ----------------
extern "C" void kernel_launch(void* const* d_in, const int* in_sizes, int n_in,
                              void* d_out, int out_size) {
    const float* ent  = (const float*)d_in[0];
    const float* gcnW = (const float*)d_in[1];
    const float* gcnB = (const float*)d_in[2];
    const float* fsW  = (const float*)d_in[3];
    const float* fsB  = (const float*)d_in[4];
    const float* feW  = (const float*)d_in[5];
    const float* feB  = (const float*)d_in[6];
    const float* disc = (const float*)d_in[7];
    const float* W1   = (const float*)d_in[8];
    const float* b1   = (const float*)d_in[9];
    const float* W2   = (const float*)d_in[10];
    const float* b2   = (const float*)d_in[11];
    const float* W3   = (const float*)d_in[12];
    const float* b3   = (const float*)d_in[13];
    const int* ss = (const int*)d_in[14];
    const int* sd = (const int*)d_in[15];
    const int* ps = (const int*)d_in[16];
    const int* pd = (const int*)d_in[17];
    const int* es = (const int*)d_in[18];
    const int* ed = (const int*)d_in[19];
    const int* exid = (const int*)d_in[21];
    const float* kn  = (const float*)d_in[22];
    const int* hid   = (const int*)d_in[23];
    const int* hseg  = (const int*)d_in[24];
    float* out = (float*)d_out;

    cudaFuncSetAttribute(k_gemmT, cudaFuncAttributeMaxDynamicSharedMemorySize, 98304);
    cudaFuncSetAttribute(k_mlp1T, cudaFuncAttributeMaxDynamicSharedMemorySize, 65536);
    cudaFuncSetAttribute(k_mlp2T, cudaFuncAttributeMaxDynamicSharedMemorySize, 114688);

    // 1: fused setup (degree atomics | init | weight conversion)
    k_setup<<<DEG_B + INIT_B + WCONV_B, 256>>>(ss, sd, ps, pd, es, ed,
                                               ent, gcnW, gcnB, W1, W2);
    // 2: scan, 3: fill, 4: agg layer 0 (ncu-profiled slot)
    k_scan<<<GN, 1024>>>();
    k_fill<<<(GN * (EE / 8) + 255) / 256, 256>>>(ss, sd, ps, pd, es, ed);

    for (int l = 0; l < 4; l++) {
        k_agg<<<(GN * NN * 32 + 255) / 256, 256>>>(l);
        k_gemmT<<<NN / 128, 256, 98304>>>(l);
    }

    k_segstart<<<(BB + 1 + 255) / 256, 256>>>(hseg);
    k_stu<<<(BB * 32 + 255) / 256, 256>>>(hid);
    k_cvec<<<1, 256>>>(fsW, feW);
    k_x<<<(BB * 32 + 255) / 256, 256>>>(fsW, fsB, feW, feB, disc, exid, kn);

    dim3 g1(BB / 128, H1 / 128);
    k_mlp1T<<<g1, 256, 65536>>>(b1);
    k_mlp2T<<<BB / 128, 256, 114688>>>(b2);
    k_outz<<<OUT_B + ZERO_B, 256>>>(W3, b3, out);
}

// round 9
// speedup vs baseline: 1.0401x; 1.0233x over previous
#include <cuda_runtime.h>
#include <cuda_fp16.h>
#include <mma.h>

using namespace nvcuda;

#define GN 3
constexpr int NN = 16512;     // K + EXER entities  (= 129 * 128 exactly)
constexpr int KD = 128;       // embedding dim
constexpr int EE = 400000;    // edges per graph (divisible by 8)
constexpr int BB = 4096;      // batch
constexpr int TT = 204800;    // history length
constexpr int H1 = 512;
constexpr int H2 = 216;
constexpr int H2P = 224;      // padded to 14*16

// block partitioning of the fused setup kernel
constexpr int DEG_B  = (GN * (EE / 8) + 255) / 256;            // 586
constexpr int INIT_B = (NN * KD / 4) / 256;                    // 2064
constexpr int WCONV_N = GN * 4 * KD * KD + KD * H1 + H1 * H2P + 4 * KD;
constexpr int WCONV_B = (WCONV_N + 255) / 256;                 // 1474
// fused head-1 kernel (segstart | cvec)
constexpr int SEG_B  = (BB + 1 + 255) / 256;                   // 17
constexpr int CVEC_B = 32;                                     // 256 warps
// k_out fused tail
constexpr int OUT_B  = (BB * 32) / 256;                        // 512
constexpr int ZERO_B = (2 * GN * NN + 255) / 256;              // 388

// ---------------- scratch (static device globals; no allocation) ----------------
// deg arrays: zero at process start (static init) and re-zeroed by the tail of
// every kernel_launch call -> each call starts from zeros deterministically.
__device__ int            d_deg_s[GN][NN];
__device__ int            d_deg_d[GN][NN];
__device__ int            d_rowp[GN][NN + 1];
__device__ int            d_cur[GN][NN];
__device__ unsigned       d_csr4[GN][EE + 16]; // src:16 | fp16 rsqrt(deg_s[src]):16
__device__ __half         d_hh0[NN * KD];  // fp16 activations (gather source)
__device__ __half         d_hh1[NN * KD];
__device__ __half         d_aggh[GN][NN * KD];   // fp16 aggregation (A for tensor GEMM)
__device__ __half         d_Wh[GN * 4 * KD * KD];// fp16 GCN weights [g][l][k][n]
__device__ float          d_biasC[4][KD];        // per-layer combined bias (sum over g)
__device__ __half         d_W1h[KD * H1];
__device__ __half         d_W2h[H1 * H2P];       // zero-padded cols
__device__ float          d_sumA[NN * KD];  // entity_emb + h1+h2+h3+h4  (full = /5)
__device__ float          d_sumL[NN * KD];  // h3 (partial)
__device__ __half         d_sumLh[NN * KD]; // h3 + h4 fp16 (disc_full*2) for k_stu
__device__ float          d_stu[BB * KD];
__device__ int            d_segs[BB + 1];
__device__ float          d_cvec[2 * KD];
__device__ __half         d_xh[BB * KD];
__device__ __half         d_x1h[BB * H1];
__device__ float          d_x2[BB * H2];

__device__ __forceinline__ float sigm(float x) { return 1.f / (1.f + __expf(-x)); }

// ---------------- fused setup: degree atomics | h0/sum init | weight conv ------
__global__ void k_setup(const int* __restrict__ s0, const int* __restrict__ d0,
                        const int* __restrict__ s1, const int* __restrict__ d1,
                        const int* __restrict__ s2, const int* __restrict__ d2,
                        const float* __restrict__ ent,
                        const float* __restrict__ gcnW, const float* __restrict__ gcnB,
                        const float* __restrict__ W1, const float* __restrict__ W2) {
    int b = blockIdx.x, tid = threadIdx.x;
    if (b < DEG_B) {
        // degree atomics, 8 edges per thread
        int i = b * 256 + tid;
        const int Q = EE / 8;
        if (i >= GN * Q) return;
        int g = i / Q, e8 = (i - g * Q) * 8;
        const int* S = (g == 0) ? s0 : (g == 1) ? s1 : s2;
        const int* D = (g == 0) ? d0 : (g == 1) ? d1 : d2;
        int4 sa = *(const int4*)&S[e8];
        int4 sb = *(const int4*)&S[e8 + 4];
        int4 da = *(const int4*)&D[e8];
        int4 db = *(const int4*)&D[e8 + 4];
        atomicAdd(&d_deg_s[g][sa.x], 1); atomicAdd(&d_deg_s[g][sa.y], 1);
        atomicAdd(&d_deg_s[g][sa.z], 1); atomicAdd(&d_deg_s[g][sa.w], 1);
        atomicAdd(&d_deg_s[g][sb.x], 1); atomicAdd(&d_deg_s[g][sb.y], 1);
        atomicAdd(&d_deg_s[g][sb.z], 1); atomicAdd(&d_deg_s[g][sb.w], 1);
        atomicAdd(&d_deg_d[g][da.x], 1); atomicAdd(&d_deg_d[g][da.y], 1);
        atomicAdd(&d_deg_d[g][da.z], 1); atomicAdd(&d_deg_d[g][da.w], 1);
        atomicAdd(&d_deg_d[g][db.x], 1); atomicAdd(&d_deg_d[g][db.y], 1);
        atomicAdd(&d_deg_d[g][db.z], 1); atomicAdd(&d_deg_d[g][db.w], 1);
    } else if (b < DEG_B + INIT_B) {
        // init: sumA=emb, sumL=0, h0=fp16(emb); 4 elems/thread
        int i = (b - DEG_B) * 256 + tid;
        float4 v = ((const float4*)ent)[i];
        ((float4*)d_sumA)[i] = v;
        ((float4*)d_sumL)[i] = make_float4(0.f, 0.f, 0.f, 0.f);
        __half2 h01 = __floats2half2_rn(v.x, v.y);
        __half2 h23 = __floats2half2_rn(v.z, v.w);
        uint2 hv;
        hv.x = *(unsigned*)&h01;
        hv.y = *(unsigned*)&h23;
        ((uint2*)d_hh0)[i] = hv;
    } else {
        // weight conversion + bias combine + W2 padding
        int i = (b - DEG_B - INIT_B) * 256 + tid;
        const int A = GN * 4 * KD * KD;
        const int B = A + KD * H1;
        const int C = B + H1 * H2P;
        const int D = C + 4 * KD;
        if (i < A) {
            d_Wh[i] = __float2half_rn(gcnW[i]);
        } else if (i < B) {
            int j = i - A;
            d_W1h[j] = __float2half_rn(W1[j]);
        } else if (i < C) {
            int j = i - B;
            int k = j / H2P, n = j - k * H2P;
            d_W2h[j] = __float2half_rn(n < H2 ? W2[k * H2 + n] : 0.f);
        } else if (i < D) {
            int j = i - C;
            int l = j >> 7, col = j & 127;
            d_biasC[l][col] = gcnB[l * KD + col] + gcnB[4 * KD + l * KD + col]
                            + gcnB[8 * KD + l * KD + col];
        }
    }
}

// exclusive scan of in-degree -> row_ptr (+cursor copy, +CSR pad zero).
__global__ void k_scan() {
    __shared__ int sA[1024], sB[1024];
    int g = blockIdx.x, t = threadIdx.x;
    const int CH = (NN + 1023) / 1024;   // 17
    int base = t * CH;
    int s = 0;
    for (int i = 0; i < CH; i++) { int idx = base + i; if (idx < NN) s += d_deg_d[g][idx]; }
    sA[t] = s;
    __syncthreads();
    int* a = sA; int* b = sB;
    for (int off = 1; off < 1024; off <<= 1) {
        b[t] = a[t] + ((t >= off) ? a[t - off] : 0);
        __syncthreads();
        int* tmp = a; a = b; b = tmp;
    }
    int incl = a[t];
    int total = a[1023];
    int run = incl - s;
    for (int i = 0; i < CH; i++) {
        int idx = base + i;
        if (idx < NN) { d_rowp[g][idx] = run; d_cur[g][idx] = run; run += d_deg_d[g][idx]; }
    }
    if (t == 0) {
        d_rowp[g][NN] = total;
        for (int q = 0; q < 16; q++) d_csr4[g][total + q] = 0;  // safe OOB pad
    }
}

// 8 edges per thread: deg_s gather + atomic cursor + 4-byte scatter
__global__ void k_fill(const int* __restrict__ s0, const int* __restrict__ d0,
                       const int* __restrict__ s1, const int* __restrict__ d1,
                       const int* __restrict__ s2, const int* __restrict__ d2) {
    int i = blockIdx.x * blockDim.x + threadIdx.x;
    const int Q = EE / 8;
    if (i >= GN * Q) return;
    int g = i / Q, e8 = (i - g * Q) * 8;
    const int* S = (g == 0) ? s0 : (g == 1) ? s1 : s2;
    const int* D = (g == 0) ? d0 : (g == 1) ? d1 : d2;
    int sv[8], dv[8];
    *(int4*)&sv[0] = *(const int4*)&S[e8];
    *(int4*)&sv[4] = *(const int4*)&S[e8 + 4];
    *(int4*)&dv[0] = *(const int4*)&D[e8];
    *(int4*)&dv[4] = *(const int4*)&D[e8 + 4];
    int ds[8];
#pragma unroll
    for (int q = 0; q < 8; q++) ds[q] = d_deg_s[g][sv[q]];
    int pos[8];
#pragma unroll
    for (int q = 0; q < 8; q++) pos[q] = atomicAdd(&d_cur[g][dv[q]], 1);
#pragma unroll
    for (int q = 0; q < 8; q++) {
        unsigned hb = (unsigned)__half_as_ushort(
            __float2half_rn(rsqrtf((float)max(ds[q], 1))));
        d_csr4[g][pos[q]] = (unsigned)sv[q] | (hb << 16);
    }
}

// ---------------- GCN aggregation: warp per (g, dst-row), fp16 + pure HFMA2 ----
// 16 lanes per edge (8 halves/lane); half-warps take 8 consecutive edges each.
// Loads are unconditional (CSR padded, OOB weight zeroed via sel) -> no clamps,
// no cvt instructions in the loop.
__global__ void __launch_bounds__(256) k_agg(int layer) {
    int gt = blockIdx.x * blockDim.x + threadIdx.x;
    int w = gt >> 5, lane = gt & 31;
    if (w >= GN * NN) return;
    int g = w / NN, n = w - g * NN;
    const __half* __restrict__ hin = (layer & 1) ? d_hh1 : d_hh0;
    int e0 = d_rowp[g][n], e1 = d_rowp[g][n + 1];
    const unsigned* __restrict__ cs = d_csr4[g];
    int hf = lane >> 4, hl = lane & 15;
    const __half* __restrict__ hcol = hin + hl * 8;
    __half2 acc[4];
#pragma unroll
    for (int j = 0; j < 4; j++) acc[j] = __floats2half2_rn(0.f, 0.f);

    for (int base = e0; base < e1; base += 16) {
        int eb = base + 8 * hf;
        unsigned r[8];
#pragma unroll
        for (int q = 0; q < 8; q++) r[q] = cs[eb + q];
        uint4 v[8];
#pragma unroll
        for (int q = 0; q < 8; q++)
            v[q] = *(const uint4*)(hcol + (int)(r[q] & 0xFFFFu) * KD);
#pragma unroll
        for (int q = 0; q < 8; q++) {
            unsigned short wb =
                (eb + q < e1) ? (unsigned short)(r[q] >> 16) : (unsigned short)0;
            __half2 w2 = __half2half2(__ushort_as_half(wb));
            const __half2* hv = (const __half2*)&v[q];
            acc[0] = __hfma2(w2, hv[0], acc[0]);
            acc[1] = __hfma2(w2, hv[1], acc[1]);
            acc[2] = __hfma2(w2, hv[2], acc[2]);
            acc[3] = __hfma2(w2, hv[3], acc[3]);
        }
    }
    // combine the two half-warps (same columns)
#pragma unroll
    for (int j = 0; j < 4; j++) {
        unsigned u = *(unsigned*)&acc[j];
        unsigned vv = __shfl_xor_sync(0xffffffffu, u, 16);
        acc[j] = __hadd2(acc[j], *(__half2*)&vv);
    }
    if (hf == 0) {
        float rsd = rsqrtf((float)max(e1 - e0, 1));   // rsqrt(deg_d) row factor
        uint4 o;
        unsigned* oo = &o.x;
#pragma unroll
        for (int j = 0; j < 4; j++) {
            float2 f = __half22float2(acc[j]);
            __half2 h = __floats2half2_rn(f.x * rsd, f.y * rsd);
            oo[j] = *(unsigned*)&h;
        }
        *(uint4*)&d_aggh[g][n * KD + hl * 8] = o;
    }
}

// ---------------- GCN GEMM (tensor cores): h_new = sum_g aggh_g @ Wh_gl + biasC
__global__ void __launch_bounds__(256) k_gemmT(int layer) {
    extern __shared__ char smem[];
    __half* Wsm = (__half*)smem;                // 3*128*128 half = 98304 B
    float* stage = (float*)smem;                // overlay after mainloop
    int tid = threadIdx.x, w = tid >> 5, lane = tid & 31;

    {
        uint4* dst = (uint4*)Wsm;
        for (int i = tid; i < 6144; i += 256) {
            int g = i >> 11, rem = i & 2047;
            dst[i] = ((const uint4*)(d_Wh + (size_t)(g * 4 + layer) * 16384))[rem];
        }
    }
    __syncthreads();

    wmma::fragment<wmma::accumulator, 16, 16, 16, float> c[8];
#pragma unroll
    for (int n = 0; n < 8; n++) wmma::fill_fragment(c[n], 0.f);

    int row0 = blockIdx.x * 128 + w * 16;
    for (int kt = 0; kt < 24; kt++) {
        int g = kt >> 3, ks = (kt & 7) << 4;
        wmma::fragment<wmma::matrix_a, 16, 16, 16, __half, wmma::row_major> a;
        wmma::load_matrix_sync(a, d_aggh[g] + row0 * KD + ks, KD);
#pragma unroll
        for (int n = 0; n < 8; n++) {
            wmma::fragment<wmma::matrix_b, 16, 16, 16, __half, wmma::row_major> b;
            wmma::load_matrix_sync(b, Wsm + g * 16384 + ks * 128 + n * 16, 128);
            wmma::mma_sync(c[n], a, b, c[n]);
        }
    }
    __syncthreads();   // everyone done reading Wsm; reuse as stage

    float* st = stage + w * 2048;
#pragma unroll
    for (int n = 0; n < 8; n++)
        wmma::store_matrix_sync(st + n * 16, c[n], 128, wmma::mem_row_major);
    __syncwarp();

    int col0 = lane * 4;
    float4 bias = *(const float4*)&d_biasC[layer][col0];
    __half* hout = (layer & 1) ? d_hh0 : d_hh1;
#pragma unroll
    for (int r = 0; r < 16; r++) {
        float4 v = *(float4*)&st[r * 128 + col0];
        v.x += bias.x; v.y += bias.y; v.z += bias.z; v.w += bias.w;
        int base = (row0 + r) * KD + col0;
        __half2 h01 = __floats2half2_rn(v.x, v.y);
        __half2 h23 = __floats2half2_rn(v.z, v.w);
        uint2 hv;
        hv.x = *(unsigned*)&h01;
        hv.y = *(unsigned*)&h23;
        *(uint2*)&hout[base] = hv;
        float4 sa = *(float4*)&d_sumA[base];
        sa.x += v.x; sa.y += v.y; sa.z += v.z; sa.w += v.w;
        *(float4*)&d_sumA[base] = sa;
        if (layer == 2) {
            *(float4*)&d_sumL[base] = v;       // h3
        } else if (layer == 3) {
            float4 sl = *(float4*)&d_sumL[base];
            __half2 s01 = __floats2half2_rn(sl.x + v.x, sl.y + v.y);
            __half2 s23 = __floats2half2_rn(sl.z + v.z, sl.w + v.w);
            uint2 sv2;
            sv2.x = *(unsigned*)&s01;
            sv2.y = *(unsigned*)&s23;
            *(uint2*)&d_sumLh[base] = sv2;     // h3+h4 fp16
        }
    }
}

// ---------------- head ----------------
// fused: segstart (binary search) | cvec (warp per dot product)
__global__ void k_head1(const int* __restrict__ seg,
                        const float* __restrict__ stuW,
                        const float* __restrict__ exeW) {
    int b = blockIdx.x, tid = threadIdx.x;
    if (b < SEG_B) {
        int i = b * 256 + tid;
        if (i > BB) return;
        int lo = 0, hi = TT;
        while (lo < hi) { int m = (lo + hi) >> 1; if (seg[m] < i) lo = m + 1; else hi = m; }
        d_segs[i] = lo;
    } else {
        int wix = (b - SEG_B) * 8 + (tid >> 5);   // 0..255
        int lanei = tid & 31;
        int j = wix & 127;
        bool isE = wix >= 128;
        const float* wv = isE ? (exeW + KD) : (stuW + KD);
        float s = 0.f;
        for (int k = lanei; k < KD; k += 32) s += d_sumA[j * KD + k] * wv[k];
#pragma unroll
        for (int o = 16; o; o >>= 1) s += __shfl_xor_sync(0xffffffffu, s, o);
        if (lanei == 0) d_cvec[(isE ? KD : 0) + j] = s * 0.2f;
    }
}

// stu[b] = mean over history of disc_full[K+hid] ; sumLh fp16 gather (8 B/lane)
__global__ void k_stu(const int* __restrict__ hist) {
    int gt = blockIdx.x * blockDim.x + threadIdx.x;
    int w = gt >> 5, lane = gt & 31;
    if (w >= BB) return;
    int s = d_segs[w], e = d_segs[w + 1];
    const __half* __restrict__ SL = d_sumLh;
    int col = lane * 4;
    float ax = 0.f, ay = 0.f, az = 0.f, aw = 0.f;
    int t = s;
    for (; t + 4 <= e; t += 4) {
        int4 h4 = make_int4(hist[t], hist[t + 1], hist[t + 2], hist[t + 3]);
        uint2 r0 = *(const uint2*)(SL + (KD + h4.x) * KD + col);
        uint2 r1 = *(const uint2*)(SL + (KD + h4.y) * KD + col);
        uint2 r2 = *(const uint2*)(SL + (KD + h4.z) * KD + col);
        uint2 r3 = *(const uint2*)(SL + (KD + h4.w) * KD + col);
        float2 f;
        f = __half22float2(*(__half2*)&r0.x); ax += f.x; ay += f.y;
        f = __half22float2(*(__half2*)&r0.y); az += f.x; aw += f.y;
        f = __half22float2(*(__half2*)&r1.x); ax += f.x; ay += f.y;
        f = __half22float2(*(__half2*)&r1.y); az += f.x; aw += f.y;
        f = __half22float2(*(__half2*)&r2.x); ax += f.x; ay += f.y;
        f = __half22float2(*(__half2*)&r2.y); az += f.x; aw += f.y;
        f = __half22float2(*(__half2*)&r3.x); ax += f.x; ay += f.y;
        f = __half22float2(*(__half2*)&r3.y); az += f.x; aw += f.y;
    }
    for (; t < e; t++) {
        int h = hist[t];
        uint2 r = *(const uint2*)(SL + (KD + h) * KD + col);
        float2 f;
        f = __half22float2(*(__half2*)&r.x); ax += f.x; ay += f.y;
        f = __half22float2(*(__half2*)&r.y); az += f.x; aw += f.y;
    }
    float inv = 0.5f / fmaxf((float)(e - s), 1.f);
    float4 o = make_float4(ax * inv, ay * inv, az * inv, aw * inv);
    *(float4*)&d_stu[w * KD + col] = o;
}

__global__ void k_x(const float* __restrict__ fsW, const float* __restrict__ fsB,
                    const float* __restrict__ feW, const float* __restrict__ feB,
                    const float* __restrict__ disc, const int* __restrict__ exid,
                    const float* __restrict__ kn) {
    int gt = blockIdx.x * blockDim.x + threadIdx.x;
    int w = gt >> 5, lane = gt & 31;
    if (w >= BB) return;
    int eid = exid[w];
    float4 sv = ((const float4*)d_stu)[w * 32 + lane];
    float4 ev = ((const float4*)d_sumA)[(KD + eid) * 32 + lane];
    float4 wa = ((const float4*)fsW)[lane];
    float4 wb = ((const float4*)feW)[lane];
    float ps = sv.x * wa.x + sv.y * wa.y + sv.z * wa.z + sv.w * wa.w;
    float pe = (ev.x * wb.x + ev.y * wb.y + ev.z * wb.z + ev.w * wb.w) * 0.2f;
#pragma unroll
    for (int o = 16; o; o >>= 1) {
        ps += __shfl_xor_sync(0xffffffffu, ps, o);
        pe += __shfl_xor_sync(0xffffffffu, pe, o);
    }
    float ed = 10.f * sigm(disc[eid]);
    float4 cs = ((const float4*)d_cvec)[lane];
    float4 ce = ((const float4*)(d_cvec + KD))[lane];
    float4 kv = ((const float4*)kn)[w * 32 + lane];
    float bs = fsB[0], be = feB[0];
    float x0 = ed * (sigm(ps + cs.x + bs) - sigm(pe + ce.x + be)) * kv.x;
    float x1 = ed * (sigm(ps + cs.y + bs) - sigm(pe + ce.y + be)) * kv.y;
    float x2 = ed * (sigm(ps + cs.z + bs) - sigm(pe + ce.z + be)) * kv.z;
    float x3 = ed * (sigm(ps + cs.w + bs) - sigm(pe + ce.w + be)) * kv.w;
    __half2 h01 = __floats2half2_rn(x0, x1);
    __half2 h23 = __floats2half2_rn(x2, x3);
    uint2 hv;
    hv.x = *(unsigned*)&h01;
    hv.y = *(unsigned*)&h23;
    *(uint2*)&d_xh[w * KD + lane * 4] = hv;
}

// MLP layer 1 (tensor): x(4096x128) @ W1(128x512) -> sigmoid -> d_x1h (fp16)
__global__ void __launch_bounds__(256) k_mlp1T(const float* __restrict__ b1) {
    extern __shared__ char smem[];
    __half* Bsm = (__half*)smem;
    float* stage = (float*)smem;
    int tid = threadIdx.x, w = tid >> 5, lane = tid & 31;
    int n0 = blockIdx.y * 128;

    for (int i = tid; i < 2048; i += 256) {
        int k = i >> 4, nq = (i & 15) << 3;
        *(uint4*)&Bsm[k * 128 + nq] = *(const uint4*)&d_W1h[k * H1 + n0 + nq];
    }
    __syncthreads();

    wmma::fragment<wmma::accumulator, 16, 16, 16, float> c[8];
#pragma unroll
    for (int n = 0; n < 8; n++) wmma::fill_fragment(c[n], 0.f);

    int row0 = blockIdx.x * 128 + w * 16;
    for (int kt = 0; kt < 8; kt++) {
        wmma::fragment<wmma::matrix_a, 16, 16, 16, __half, wmma::row_major> a;
        wmma::load_matrix_sync(a, d_xh + row0 * KD + kt * 16, KD);
#pragma unroll
        for (int n = 0; n < 8; n++) {
            wmma::fragment<wmma::matrix_b, 16, 16, 16, __half, wmma::row_major> b;
            wmma::load_matrix_sync(b, Bsm + kt * 16 * 128 + n * 16, 128);
            wmma::mma_sync(c[n], a, b, c[n]);
        }
    }
    __syncthreads();

    float* st = stage + w * 2048;
#pragma unroll
    for (int n = 0; n < 8; n++)
        wmma::store_matrix_sync(st + n * 16, c[n], 128, wmma::mem_row_major);
    __syncwarp();

    int col0 = lane * 4;
    float4 bias = *(const float4*)&b1[n0 + col0];
#pragma unroll
    for (int r = 0; r < 16; r++) {
        float4 v = *(float4*)&st[r * 128 + col0];
        float y0 = sigm(v.x + bias.x);
        float y1 = sigm(v.y + bias.y);
        float y2 = sigm(v.z + bias.z);
        float y3 = sigm(v.w + bias.w);
        __half2 h01 = __floats2half2_rn(y0, y1);
        __half2 h23 = __floats2half2_rn(y2, y3);
        uint2 hv;
        hv.x = *(unsigned*)&h01;
        hv.y = *(unsigned*)&h23;
        *(uint2*)&d_x1h[(row0 + r) * H1 + n0 + col0] = hv;
    }
}

// MLP layer 2 (tensor): x1(4096x512) @ W2pad(512x224) -> sigmoid -> d_x2 (fp32, 216 cols)
__global__ void __launch_bounds__(256) k_mlp2T(const float* __restrict__ b2) {
    extern __shared__ float stage[];    // 8 * 16 * 224 floats = 114688 B
    int tid = threadIdx.x, w = tid >> 5, lane = tid & 31;

    wmma::fragment<wmma::accumulator, 16, 16, 16, float> c[14];
#pragma unroll
    for (int n = 0; n < 14; n++) wmma::fill_fragment(c[n], 0.f);

    int row0 = blockIdx.x * 128 + w * 16;
    for (int kt = 0; kt < 32; kt++) {
        wmma::fragment<wmma::matrix_a, 16, 16, 16, __half, wmma::row_major> a;
        wmma::load_matrix_sync(a, d_x1h + row0 * H1 + kt * 16, H1);
#pragma unroll
        for (int n = 0; n < 14; n++) {
            wmma::fragment<wmma::matrix_b, 16, 16, 16, __half, wmma::row_major> b;
            wmma::load_matrix_sync(b, d_W2h + kt * 16 * H2P + n * 16, H2P);
            wmma::mma_sync(c[n], a, b, c[n]);
        }
    }
    float* st = stage + w * (16 * H2P);
#pragma unroll
    for (int n = 0; n < 14; n++)
        wmma::store_matrix_sync(st + n * 16, c[n], H2P, wmma::mem_row_major);
    __syncwarp();

#pragma unroll
    for (int j = 0; j < 7; j++) {
        int col = lane * 7 + j;
        if (col < H2) {
            float bb = b2[col];
#pragma unroll
            for (int r = 0; r < 16; r++) {
                float v = st[r * H2P + col];
                d_x2[(row0 + r) * H2 + col] = sigm(v + bb);
            }
        }
    }
}

// output + deg-array re-zero for the next call (fused tail)
__global__ void k_outz(const float* __restrict__ W3, const float* __restrict__ b3,
                       float* __restrict__ out) {
    int b = blockIdx.x, tid = threadIdx.x;
    if (b < OUT_B) {
        int gt = b * 256 + tid;
        int w = gt >> 5, lane = gt & 31;
        if (w >= BB) return;
        float s = 0.f;
        for (int k = lane; k < H2; k += 32) s += d_x2[w * H2 + k] * W3[k];
#pragma unroll
        for (int o = 16; o; o >>= 1) s += __shfl_xor_sync(0xffffffffu, s, o);
        if (lane == 0) out[w] = sigm(s + b3[0]);
    } else {
        int i = (b - OUT_B) * 256 + tid;
        if (i < GN * NN) ((int*)d_deg_s)[i] = 0;
        else if (i < 2 * GN * NN) ((int*)d_deg_d)[i - GN * NN] = 0;
    }
}

// ---------------- launch ----------------
extern "C" void kernel_launch(void* const* d_in, const int* in_sizes, int n_in,
                              void* d_out, int out_size) {
    const float* ent  = (const float*)d_in[0];
    const float* gcnW = (const float*)d_in[1];
    const float* gcnB = (const float*)d_in[2];
    const float* fsW  = (const float*)d_in[3];
    const float* fsB  = (const float*)d_in[4];
    const float* feW  = (const float*)d_in[5];
    const float* feB  = (const float*)d_in[6];
    const float* disc = (const float*)d_in[7];
    const float* W1   = (const float*)d_in[8];
    const float* b1   = (const float*)d_in[9];
    const float* W2   = (const float*)d_in[10];
    const float* b2   = (const float*)d_in[11];
    const float* W3   = (const float*)d_in[12];
    const float* b3   = (const float*)d_in[13];
    const int* ss = (const int*)d_in[14];
    const int* sd = (const int*)d_in[15];
    const int* ps = (const int*)d_in[16];
    const int* pd = (const int*)d_in[17];
    const int* es = (const int*)d_in[18];
    const int* ed = (const int*)d_in[19];
    const int* exid = (const int*)d_in[21];
    const float* kn  = (const float*)d_in[22];
    const int* hid   = (const int*)d_in[23];
    const int* hseg  = (const int*)d_in[24];
    float* out = (float*)d_out;

    cudaFuncSetAttribute(k_gemmT, cudaFuncAttributeMaxDynamicSharedMemorySize, 98304);
    cudaFuncSetAttribute(k_mlp1T, cudaFuncAttributeMaxDynamicSharedMemorySize, 65536);
    cudaFuncSetAttribute(k_mlp2T, cudaFuncAttributeMaxDynamicSharedMemorySize, 114688);

    // 1: fused setup (degree atomics | init | weight conversion)
    k_setup<<<DEG_B + INIT_B + WCONV_B, 256>>>(ss, sd, ps, pd, es, ed,
                                               ent, gcnW, gcnB, W1, W2);
    // 2: scan, 3: fill, 4: agg layer 0 (ncu-profiled slot)
    k_scan<<<GN, 1024>>>();
    k_fill<<<(GN * (EE / 8) + 255) / 256, 256>>>(ss, sd, ps, pd, es, ed);

    for (int l = 0; l < 4; l++) {
        k_agg<<<(GN * NN * 32 + 255) / 256, 256>>>(l);
        k_gemmT<<<NN / 128, 256, 98304>>>(l);
    }

    k_head1<<<SEG_B + CVEC_B, 256>>>(hseg, fsW, feW);
    k_stu<<<(BB * 32 + 255) / 256, 256>>>(hid);
    k_x<<<(BB * 32 + 255) / 256, 256>>>(fsW, fsB, feW, feB, disc, exid, kn);

    dim3 g1(BB / 128, H1 / 128);
    k_mlp1T<<<g1, 256, 65536>>>(b1);
    k_mlp2T<<<BB / 128, 256, 114688>>>(b2);
    k_outz<<<OUT_B + ZERO_B, 256>>>(W3, b3, out);
}